// round 13
// baseline (speedup 1.0000x reference)
#include <cuda_runtime.h>
#include <math.h>

#define NN    131072      // nodes
#define NE    1048576     // edges
#define HDIM  64
#define NL    3
#define RD    128
#define JKD   192
#define BGR   256         // graphs
#define NPER  512         // nodes per graph (= seq len)
#define G3R   384         // 3*R

// ---------------- static device scratch ----------------
__device__ float g_xp[NN * HDIM];
__device__ float g_hjk[NN * JKD];
__device__ float g_as[NN];
__device__ float g_ad[NN];
__device__ int   g_deg[NN];
__device__ int   g_rowoff[NN + 1];
__device__ int   g_cursor[NN];
__device__ int   g_src[NE];
__device__ int   g_dst[NE];
__device__ float4 g_pack[NE];       // CSR-ordered {src_bits, se0, se1, se2}
__device__ float g_gx[2][(size_t)NN * G3R];
__device__ float g_y2[(size_t)NN * 256];
__device__ float g_ew[NL][2];
__device__ float g_ec[NL];
__device__ int   g_is64;

__device__ __forceinline__ float lrelu02(float x)  { return x > 0.f ? x : 0.2f  * x; }
__device__ __forceinline__ float lrelu001(float x) { return x > 0.f ? x : 0.01f * x; }
__device__ __forceinline__ float sigm(float x) { return 1.f / (1.f + __expf(-x)); }
__device__ __forceinline__ float tanh_(float x) { return 1.f - 2.f / (1.f + __expf(2.f * x)); }

__device__ __forceinline__ float* bufptr(int sel) {
    switch (sel) {
        case 1: return g_hjk;
        case 2: return g_xp;
        case 3: return g_gx[0];
        case 4: return g_y2;
    }
    return nullptr;
}

__device__ __forceinline__ unsigned f2tf(float x) {
    unsigned r;
    asm("cvt.rna.tf32.f32 %0, %1;" : "=r"(r) : "f"(x));
    return r;
}

__device__ __forceinline__ unsigned long long fma2(unsigned long long a,
                                                   unsigned long long b,
                                                   unsigned long long c) {
    unsigned long long d;
    asm("fma.rn.f32x2 %0, %1, %2, %3;" : "=l"(d) : "l"(a), "l"(b), "l"(c));
    return d;
}

__device__ __forceinline__ float sum2(unsigned long long a) {
    float x, y;
    asm("mov.b64 {%0,%1}, %2;" : "=f"(x), "=f"(y) : "l"(a));
    return x + y;
}

__device__ __forceinline__ void mma8(float* d, const unsigned* a, unsigned b0, unsigned b1) {
    asm volatile(
        "mma.sync.aligned.m16n8k8.row.col.f32.tf32.tf32.f32 "
        "{%0,%1,%2,%3}, {%4,%5,%6,%7}, {%8,%9}, {%0,%1,%2,%3};\n"
        : "+f"(d[0]), "+f"(d[1]), "+f"(d[2]), "+f"(d[3])
        : "r"(a[0]), "r"(a[1]), "r"(a[2]), "r"(a[3]), "r"(b0), "r"(b1));
}

__device__ __forceinline__ void split32(float v, unsigned& hi, unsigned& lo) {
    unsigned b = __float_as_uint(v);
    hi = b & 0xFFFFE000u;
    float l = v - __uint_as_float(hi);
    lo = f2tf(l);
}

// ---------------- small kernels ----------------
__global__ void detect_kernel(const int* raw) {
    __shared__ int s;
    int t = threadIdx.x;               // 256
    if (t == 0) s = 0;
    __syncthreads();
    if (raw[2 * t + 1] != 0) atomicOr(&s, 1);
    __syncthreads();
    if (t == 0) g_is64 = s ? 0 : 1;
}

__global__ void zero_init_kernel() {
    int i = blockIdx.x * blockDim.x + threadIdx.x;
    if (i >= NN) return;
    g_deg[i] = 0;
    g_cursor[i] = 0;
}

__global__ void convert_edges(const void* eidx) {
    int e = blockIdx.x * blockDim.x + threadIdx.x;
    if (e >= NE) return;
    int s, d;
    if (g_is64) {
        const long long* p = (const long long*)eidx;
        s = (int)p[e];
        d = (int)p[(size_t)NE + e];
    } else {
        const int* p = (const int*)eidx;
        s = p[e];
        d = p[NE + e];
    }
    g_src[e] = s;
    g_dst[e] = d;
    atomicAdd(&g_deg[d], 1);
}

// one block per layer; v = We_l @ ae_l, then 3 dot products
__global__ void precomp_kernel(const float* __restrict__ We, const float* __restrict__ ae,
                               const float* __restrict__ eW, const float* __restrict__ eb) {
    __shared__ float v[64];
    int l = blockIdx.x;
    int t = threadIdx.x;   // 64
    float s = 0.f;
    #pragma unroll
    for (int j = 0; j < 64; j++) s += We[l * 4096 + t * 64 + j] * ae[l * 64 + j];
    v[t] = s;
    __syncthreads();
    if (t < 32) {
        float e0 = 0.f, e1 = 0.f, c = 0.f;
        #pragma unroll
        for (int k = t; k < 64; k += 32) {
            e0 += eW[k]      * v[k];
            e1 += eW[64 + k] * v[k];
            c  += eb[k]      * v[k];
        }
        #pragma unroll
        for (int o = 16; o; o >>= 1) {
            e0 += __shfl_xor_sync(~0u, e0, o);
            e1 += __shfl_xor_sync(~0u, e1, o);
            c  += __shfl_xor_sync(~0u, c, o);
        }
        if (t == 0) { g_ew[l][0] = e0; g_ew[l][1] = e1; g_ec[l] = c; }
    }
}

__global__ void scan_kernel() {
    __shared__ int sh[1024];
    int tid = threadIdx.x;
    int base = tid * (NN / 1024);
    int s = 0;
    for (int i = 0; i < NN / 1024; i++) s += g_deg[base + i];
    sh[tid] = s;
    __syncthreads();
    for (int off = 1; off < 1024; off <<= 1) {
        int v = (tid >= off) ? sh[tid - off] : 0;
        __syncthreads();
        sh[tid] += v;
        __syncthreads();
    }
    int run = sh[tid] - s;
    for (int i = 0; i < NN / 1024; i++) {
        g_rowoff[base + i] = run;
        run += g_deg[base + i];
    }
    if (tid == 1023) g_rowoff[NN] = sh[1023];
}

// CSR fill: ONE 16B packed store per edge {src, se0, se1, se2}
__global__ void fill_csr_kernel(const float* __restrict__ edge_attr) {
    int e = blockIdx.x * blockDim.x + threadIdx.x;
    if (e >= NE) return;
    int d = g_dst[e];
    int pos = g_rowoff[d] + atomicAdd(&g_cursor[d], 1);
    float ea0 = edge_attr[2 * e], ea1 = edge_attr[2 * e + 1];
    float4 p;
    p.x = __int_as_float(g_src[e]);
    p.y = ea0 * g_ew[0][0] + ea1 * g_ew[0][1] + g_ec[0];
    p.z = ea0 * g_ew[1][0] + ea1 * g_ew[1][1] + g_ec[1];
    p.w = ea0 * g_ew[2][0] + ea1 * g_ew[2][1] + g_ec[2];
    g_pack[pos] = p;
}

// ---------------- tf32 tensor-core GEMM: 128x64 tile, double-buffered (head path) ---------
#define PADA 136
#define PADB 72
__global__ __launch_bounds__(256) void tgemm(
    int Asel, long aoff, int lda,
    const float* __restrict__ B, int ldb,
    int Csel, long coff, int ldc, int K,
    const float* __restrict__ bias, int act,
    const float* __restrict__ W2, const float* __restrict__ b2,
    float* __restrict__ outp)
{
    const float* A = bufptr(Asel) + aoff;
    float*       C = (act == 2) ? nullptr : (bufptr(Csel) + coff);

    __shared__ unsigned As[2][16][PADA];
    __shared__ unsigned Bs[2][16][PADB];
    __shared__ float sm_o[128][2];

    int tid = threadIdx.x;
    int warp = tid >> 5, lane = tid & 31;
    int wm = (warp & 3) * 32;
    int wn = (warp >> 2) * 32;
    int g = lane >> 2, tg = lane & 3;

    long mBase = (long)blockIdx.y * 128;
    int  nBase = blockIdx.x * 64;

    float acc[2][4][4] = {};

    int arow = tid >> 1, acol = (tid & 1) * 8;
    const float* Aptr = A + (mBase + arow) * lda + acol;
    int bkN = tid >> 4, bnN = (tid & 15) * 4;

    int T = K / 16;

    float4 sa0, sa1, sb;
    sa0 = *(const float4*)(Aptr);
    sa1 = *(const float4*)(Aptr + 4);
    sb  = *(const float4*)(B + (long)bkN * ldb + nBase + bnN);

    As[0][acol + 0][arow] = f2tf(sa0.x);
    As[0][acol + 1][arow] = f2tf(sa0.y);
    As[0][acol + 2][arow] = f2tf(sa0.z);
    As[0][acol + 3][arow] = f2tf(sa0.w);
    As[0][acol + 4][arow] = f2tf(sa1.x);
    As[0][acol + 5][arow] = f2tf(sa1.y);
    As[0][acol + 6][arow] = f2tf(sa1.z);
    As[0][acol + 7][arow] = f2tf(sa1.w);
    Bs[0][bkN][bnN + 0] = f2tf(sb.x);
    Bs[0][bkN][bnN + 1] = f2tf(sb.y);
    Bs[0][bkN][bnN + 2] = f2tf(sb.z);
    Bs[0][bkN][bnN + 3] = f2tf(sb.w);
    __syncthreads();

    for (int t = 0; t < T; t++) {
        int buf = t & 1;
        if (t + 1 < T) {
            int kt = (t + 1) * 16;
            sa0 = *(const float4*)(Aptr + kt);
            sa1 = *(const float4*)(Aptr + kt + 4);
            sb  = *(const float4*)(B + (long)(kt + bkN) * ldb + nBase + bnN);
        }

        #pragma unroll
        for (int kk = 0; kk < 16; kk += 8) {
            unsigned a[2][4], b[4][2];
            #pragma unroll
            for (int mi = 0; mi < 2; mi++) {
                int m0 = wm + mi * 16;
                a[mi][0] = As[buf][kk + tg]    [m0 + g];
                a[mi][1] = As[buf][kk + tg]    [m0 + g + 8];
                a[mi][2] = As[buf][kk + tg + 4][m0 + g];
                a[mi][3] = As[buf][kk + tg + 4][m0 + g + 8];
            }
            #pragma unroll
            for (int ni = 0; ni < 4; ni++) {
                b[ni][0] = Bs[buf][kk + tg]    [wn + ni * 8 + g];
                b[ni][1] = Bs[buf][kk + tg + 4][wn + ni * 8 + g];
            }
            #pragma unroll
            for (int mi = 0; mi < 2; mi++)
                #pragma unroll
                for (int ni = 0; ni < 4; ni++)
                    mma8(acc[mi][ni], a[mi], b[ni][0], b[ni][1]);
        }

        if (t + 1 < T) {
            int nb = buf ^ 1;
            As[nb][acol + 0][arow] = f2tf(sa0.x);
            As[nb][acol + 1][arow] = f2tf(sa0.y);
            As[nb][acol + 2][arow] = f2tf(sa0.z);
            As[nb][acol + 3][arow] = f2tf(sa0.w);
            As[nb][acol + 4][arow] = f2tf(sa1.x);
            As[nb][acol + 5][arow] = f2tf(sa1.y);
            As[nb][acol + 6][arow] = f2tf(sa1.z);
            As[nb][acol + 7][arow] = f2tf(sa1.w);
            Bs[nb][bkN][bnN + 0] = f2tf(sb.x);
            Bs[nb][bkN][bnN + 1] = f2tf(sb.y);
            Bs[nb][bkN][bnN + 2] = f2tf(sb.z);
            Bs[nb][bkN][bnN + 3] = f2tf(sb.w);
        }
        __syncthreads();
    }

    if (act == 2) {
        if (tid < 128) { sm_o[tid][0] = 0.f; sm_o[tid][1] = 0.f; }
        __syncthreads();
        float po[2][2][2] = {};
        #pragma unroll
        for (int mi = 0; mi < 2; mi++)
            #pragma unroll
            for (int ni = 0; ni < 4; ni++) {
                int col = nBase + wn + ni * 8 + tg * 2;
                float b0 = bias[col], b1 = bias[col + 1];
                float w00 = W2[col * 2],       w01 = W2[col * 2 + 1];
                float w10 = W2[(col + 1) * 2], w11 = W2[(col + 1) * 2 + 1];
                #pragma unroll
                for (int r = 0; r < 2; r++) {
                    float v0 = fmaxf(acc[mi][ni][2 * r]     + b0, 0.f);
                    float v1 = fmaxf(acc[mi][ni][2 * r + 1] + b1, 0.f);
                    po[mi][r][0] += v0 * w00 + v1 * w10;
                    po[mi][r][1] += v0 * w01 + v1 * w11;
                }
            }
        #pragma unroll
        for (int mi = 0; mi < 2; mi++)
            #pragma unroll
            for (int r = 0; r < 2; r++)
                #pragma unroll
                for (int o = 0; o < 2; o++) {
                    po[mi][r][o] += __shfl_xor_sync(~0u, po[mi][r][o], 1);
                    po[mi][r][o] += __shfl_xor_sync(~0u, po[mi][r][o], 2);
                }
        if (tg == 0) {
            #pragma unroll
            for (int mi = 0; mi < 2; mi++)
                #pragma unroll
                for (int r = 0; r < 2; r++) {
                    int rl = wm + mi * 16 + g + r * 8;
                    atomicAdd(&sm_o[rl][0], po[mi][r][0]);
                    atomicAdd(&sm_o[rl][1], po[mi][r][1]);
                }
        }
        __syncthreads();
        if (tid < 128) {
            long row = mBase + tid;
            *(float2*)(outp + row * 2) =
                make_float2(sm_o[tid][0] + b2[0], sm_o[tid][1] + b2[1]);
        }
        return;
    }

    #pragma unroll
    for (int mi = 0; mi < 2; mi++)
        #pragma unroll
        for (int ni = 0; ni < 4; ni++) {
            int col = nBase + wn + ni * 8 + tg * 2;
            float b0 = bias ? bias[col]     : 0.f;
            float b1 = bias ? bias[col + 1] : 0.f;
            #pragma unroll
            for (int r = 0; r < 2; r++) {
                long row = mBase + wm + mi * 16 + g + r * 8;
                float v0 = acc[mi][ni][2 * r]     + b0;
                float v1 = acc[mi][ni][2 * r + 1] + b1;
                if (act == 1) { v0 = fmaxf(v0, 0.f); v1 = fmaxf(v1, 0.f); }
                *(float2*)(C + row * ldc + col) = make_float2(v0, v1);
            }
        }
}

// ---------------- wih GEMM, BOTH directions, fragment-major smem layout (R9 version) ----
__global__ __launch_bounds__(256) void tgemmW2(
    const float* __restrict__ Bf, const float* __restrict__ biasf,
    const float* __restrict__ Bb, const float* __restrict__ biasb)
{
    __shared__ __align__(16) unsigned Af[2][8][2][136];
    __shared__ __align__(8)  unsigned BsF[2][8][2][68];
    __shared__ __align__(8)  unsigned BsB[2][8][2][68];

    int tid = threadIdx.x;
    int warp = tid >> 5, lane = tid & 31;
    int mtb = (warp & 3) * 2;
    int ntb = (warp >> 2) * 4;

    long mBase = (long)blockIdx.y * 128;
    int  nBase = blockIdx.x * 64;

    float accF[2][4][4] = {};
    float accB[2][4][4] = {};

    int arow = tid >> 1, ab = tid & 1;
    int amt = arow >> 4, ag = arow & 7, arh = (arow >> 3) & 1;
    const float* Aptr = g_hjk + (mBase + arow) * JKD + ab * 8;

    int bn = tid >> 2;
    int bb_ = (tid & 3) >> 1, bh = tid & 1;
    int bnt = bn >> 3, bg = bn & 7;
    const float* BfPtr = Bf + (long)(nBase + bn) * JKD + bb_ * 8 + bh * 4;
    const float* BbPtr = Bb + (long)(nBase + bn) * JKD + bb_ * 8 + bh * 4;

    const int T = JKD / 16;

    float4 sa0 = *(const float4*)(Aptr);
    float4 sa1 = *(const float4*)(Aptr + 4);
    float4 sbf = *(const float4*)(BfPtr);
    float4 sbb = *(const float4*)(BbPtr);

    {
        float va[8] = {sa0.x, sa0.y, sa0.z, sa0.w, sa1.x, sa1.y, sa1.z, sa1.w};
        #pragma unroll
        for (int j = 0; j < 8; j++) {
            int tg = j & 3, h = j >> 2;
            Af[0][amt][ab][(ag * 4 + tg) * 4 + arh + 2 * h] = f2tf(va[j]);
        }
        float vf[4] = {sbf.x, sbf.y, sbf.z, sbf.w};
        float vb[4] = {sbb.x, sbb.y, sbb.z, sbb.w};
        #pragma unroll
        for (int tg = 0; tg < 4; tg++) {
            BsF[0][bnt][bb_][(bg * 4 + tg) * 2 + bh] = f2tf(vf[tg]);
            BsB[0][bnt][bb_][(bg * 4 + tg) * 2 + bh] = f2tf(vb[tg]);
        }
    }
    __syncthreads();

    for (int t = 0; t < T; t++) {
        int buf = t & 1;
        if (t + 1 < T) {
            int kt = (t + 1) * 16;
            sa0 = *(const float4*)(Aptr + kt);
            sa1 = *(const float4*)(Aptr + kt + 4);
            sbf = *(const float4*)(BfPtr + kt);
            sbb = *(const float4*)(BbPtr + kt);
        }

        #pragma unroll
        for (int b = 0; b < 2; b++) {
            unsigned a[2][4];
            uint2 fb[4], bbr[4];
            #pragma unroll
            for (int mi = 0; mi < 2; mi++)
                *(uint4*)a[mi] = *(const uint4*)&Af[buf][mtb + mi][b][lane * 4];
            #pragma unroll
            for (int ni = 0; ni < 4; ni++) {
                fb[ni]  = *(const uint2*)&BsF[buf][ntb + ni][b][lane * 2];
                bbr[ni] = *(const uint2*)&BsB[buf][ntb + ni][b][lane * 2];
            }
            #pragma unroll
            for (int mi = 0; mi < 2; mi++)
                #pragma unroll
                for (int ni = 0; ni < 4; ni++) {
                    mma8(accF[mi][ni], a[mi], fb[ni].x, fb[ni].y);
                    mma8(accB[mi][ni], a[mi], bbr[ni].x, bbr[ni].y);
                }
        }

        if (t + 1 < T) {
            int nb = buf ^ 1;
            float va[8] = {sa0.x, sa0.y, sa0.z, sa0.w, sa1.x, sa1.y, sa1.z, sa1.w};
            #pragma unroll
            for (int j = 0; j < 8; j++) {
                int tg = j & 3, h = j >> 2;
                Af[nb][amt][ab][(ag * 4 + tg) * 4 + arh + 2 * h] = f2tf(va[j]);
            }
            float vf[4] = {sbf.x, sbf.y, sbf.z, sbf.w};
            float vb[4] = {sbb.x, sbb.y, sbb.z, sbb.w};
            #pragma unroll
            for (int tg = 0; tg < 4; tg++) {
                BsF[nb][bnt][bb_][(bg * 4 + tg) * 2 + bh] = f2tf(vf[tg]);
                BsB[nb][bnt][bb_][(bg * 4 + tg) * 2 + bh] = f2tf(vb[tg]);
            }
        }
        __syncthreads();
    }

    int g = lane >> 2, tg = lane & 3;
    float* Cf = g_gx[0];
    float* Cb = g_gx[1];
    #pragma unroll
    for (int mi = 0; mi < 2; mi++)
        #pragma unroll
        for (int ni = 0; ni < 4; ni++) {
            int col = nBase + (ntb + ni) * 8 + tg * 2;
            float bf0 = biasf[col], bf1 = biasf[col + 1];
            float bb0 = biasb[col], bb1 = biasb[col + 1];
            #pragma unroll
            for (int r = 0; r < 2; r++) {
                long row = mBase + (mtb + mi) * 16 + g + r * 8;
                *(float2*)(Cf + row * G3R + col) =
                    make_float2(accF[mi][ni][2 * r] + bf0, accF[mi][ni][2 * r + 1] + bf1);
                *(float2*)(Cb + row * G3R + col) =
                    make_float2(accB[mi][ni][2 * r] + bb0, accB[mi][ni][2 * r + 1] + bb1);
            }
        }
}

// ---------------- 3xTF32 GEMM (fp32-accurate) for GAT xp, fused a_s/a_d epilogue -------
__global__ __launch_bounds__(256) void tgemm3(
    int Asel, long aoff, int lda,
    const float* __restrict__ B, int ldb, int K,
    const float* __restrict__ atts, const float* __restrict__ attd,
    const float* __restrict__ x, const float* __restrict__ nW,
    const float* __restrict__ nb)
{
    float* C = g_xp;

    __shared__ unsigned Ah[16][PADA], Al[16][PADA];
    __shared__ unsigned Bh[16][PADB], Bl[16][PADB];
    __shared__ float sm_ad[128][2];

    int tid = threadIdx.x;
    int warp = tid >> 5, lane = tid & 31;
    int wm = (warp & 3) * 32;
    int wn = (warp >> 2) * 32;
    int g = lane >> 2, tg = lane & 3;

    long mBase = (long)blockIdx.y * 128;
    int  nBase = blockIdx.x * 64;

    float acc[2][4][4] = {};

    int arow = tid >> 1, acol = (tid & 1) * 8;
    bool emb = (Asel == 0);
    const float* Aptr = emb ? nullptr : (bufptr(Asel) + aoff + (mBase + arow) * lda + acol);
    float2 xr = emb ? *(const float2*)(x + 2 * (mBase + arow)) : make_float2(0.f, 0.f);
    int bkN = tid >> 4, bnN = (tid & 15) * 4;

    if (tid < 128) { sm_ad[tid][0] = 0.f; sm_ad[tid][1] = 0.f; }

    for (int kt = 0; kt < K; kt += 16) {
        float va[8];
        if (emb) {
            #pragma unroll
            for (int j = 0; j < 8; j++) {
                int c = kt + acol + j;
                va[j] = xr.x * nW[c] + xr.y * nW[64 + c] + nb[c];
            }
        } else {
            float4 a0 = *(const float4*)(Aptr + kt);
            float4 a1 = *(const float4*)(Aptr + kt + 4);
            va[0] = a0.x; va[1] = a0.y; va[2] = a0.z; va[3] = a0.w;
            va[4] = a1.x; va[5] = a1.y; va[6] = a1.z; va[7] = a1.w;
        }
        float4 b4 = *(const float4*)(B + (long)(kt + bkN) * ldb + nBase + bnN);
        __syncthreads();

        unsigned h, l;
        #pragma unroll
        for (int j = 0; j < 8; j++) {
            split32(va[j], h, l);
            Ah[acol + j][arow] = h; Al[acol + j][arow] = l;
        }
        split32(b4.x, h, l); Bh[bkN][bnN + 0] = h; Bl[bkN][bnN + 0] = l;
        split32(b4.y, h, l); Bh[bkN][bnN + 1] = h; Bl[bkN][bnN + 1] = l;
        split32(b4.z, h, l); Bh[bkN][bnN + 2] = h; Bl[bkN][bnN + 2] = l;
        split32(b4.w, h, l); Bh[bkN][bnN + 3] = h; Bl[bkN][bnN + 3] = l;
        __syncthreads();

        #pragma unroll
        for (int kk = 0; kk < 16; kk += 8) {
            unsigned ah[2][4], al[2][4], bh[4][2], bl[4][2];
            #pragma unroll
            for (int mi = 0; mi < 2; mi++) {
                int m0 = wm + mi * 16;
                ah[mi][0] = Ah[kk + tg]    [m0 + g];
                ah[mi][1] = Ah[kk + tg]    [m0 + g + 8];
                ah[mi][2] = Ah[kk + tg + 4][m0 + g];
                ah[mi][3] = Ah[kk + tg + 4][m0 + g + 8];
                al[mi][0] = Al[kk + tg]    [m0 + g];
                al[mi][1] = Al[kk + tg]    [m0 + g + 8];
                al[mi][2] = Al[kk + tg + 4][m0 + g];
                al[mi][3] = Al[kk + tg + 4][m0 + g + 8];
            }
            #pragma unroll
            for (int ni = 0; ni < 4; ni++) {
                bh[ni][0] = Bh[kk + tg]    [wn + ni * 8 + g];
                bh[ni][1] = Bh[kk + tg + 4][wn + ni * 8 + g];
                bl[ni][0] = Bl[kk + tg]    [wn + ni * 8 + g];
                bl[ni][1] = Bl[kk + tg + 4][wn + ni * 8 + g];
            }
            #pragma unroll
            for (int mi = 0; mi < 2; mi++)
                #pragma unroll
                for (int ni = 0; ni < 4; ni++) {
                    mma8(acc[mi][ni], ah[mi], bh[ni][0], bh[ni][1]);
                    mma8(acc[mi][ni], ah[mi], bl[ni][0], bl[ni][1]);
                    mma8(acc[mi][ni], al[mi], bh[ni][0], bh[ni][1]);
                }
        }
    }

    float ps[2][2] = {}, pd[2][2] = {};
    #pragma unroll
    for (int mi = 0; mi < 2; mi++)
        #pragma unroll
        for (int ni = 0; ni < 4; ni++) {
            int col = nBase + wn + ni * 8 + tg * 2;
            float as0 = atts[col], as1 = atts[col + 1];
            float ad0 = attd[col], ad1 = attd[col + 1];
            #pragma unroll
            for (int r = 0; r < 2; r++) {
                long row = mBase + wm + mi * 16 + g + r * 8;
                float v0 = acc[mi][ni][2 * r], v1 = acc[mi][ni][2 * r + 1];
                *(float2*)(C + row * 64 + col) = make_float2(v0, v1);
                ps[mi][r] += v0 * as0 + v1 * as1;
                pd[mi][r] += v0 * ad0 + v1 * ad1;
            }
        }
    #pragma unroll
    for (int mi = 0; mi < 2; mi++)
        #pragma unroll
        for (int r = 0; r < 2; r++) {
            ps[mi][r] += __shfl_xor_sync(~0u, ps[mi][r], 1);
            ps[mi][r] += __shfl_xor_sync(~0u, ps[mi][r], 2);
            pd[mi][r] += __shfl_xor_sync(~0u, pd[mi][r], 1);
            pd[mi][r] += __shfl_xor_sync(~0u, pd[mi][r], 2);
        }
    if (tg == 0) {
        #pragma unroll
        for (int mi = 0; mi < 2; mi++)
            #pragma unroll
            for (int r = 0; r < 2; r++) {
                int rl = wm + mi * 16 + g + r * 8;
                atomicAdd(&sm_ad[rl][0], ps[mi][r]);
                atomicAdd(&sm_ad[rl][1], pd[mi][r]);
            }
    }
    __syncthreads();
    if (tid < 128) {
        g_as[mBase + tid] = sm_ad[tid][0];
        g_ad[mBase + tid] = sm_ad[tid][1];
    }
}

// GAT softmax + aggregation: 2-pass (no max subtraction; alphas are O(0.1), exp safe)
#define MAXDN 64
__global__ void gat_agg_kernel(int l, const float* __restrict__ atb) {
    int w = threadIdx.x >> 5, lane = threadIdx.x & 31;
    int n = blockIdx.x * 8 + w;
    if (n >= NN) return;

    __shared__ float s_ex[8][MAXDN];
    __shared__ int   s_src[8][MAXDN];

    int off = g_rowoff[n];
    int dn = g_rowoff[n + 1] - off;
    float adn = g_ad[n];
    bool cached = (dn <= MAXDN);

    // pass A: exp(alpha) directly, accumulate den and sum_se
    float den = 0.f, sum_se = 0.f;
    for (int i = lane; i < dn; i += 32) {
        float4 p = g_pack[off + i];
        int s = __float_as_int(p.x);
        float se = (l == 0) ? p.y : ((l == 1) ? p.z : p.w);
        float ex = __expf(lrelu02(g_as[s] + adn + se));
        sum_se += se;
        den += ex;
        if (cached) { s_ex[w][i] = ex; s_src[w][i] = s; }
    }
    #pragma unroll
    for (int o = 16; o; o >>= 1) {
        den += __shfl_xor_sync(~0u, den, o);
        sum_se += __shfl_xor_sync(~0u, sum_se, o);
    }
    float loopv = sum_se / (float)max(dn, 1);
    float eself = __expf(lrelu02(g_as[n] + adn + loopv));
    den += eself;
    float inv = 1.f / den;
    __syncwarp();

    // pass B: weighted aggregation, 8-wide unroll
    float a0 = eself * inv * g_xp[n * 64 + lane];
    float a1 = eself * inv * g_xp[n * 64 + lane + 32];
    if (cached) {
        int i = 0;
        for (; i + 8 <= dn; i += 8) {
            float wt[8];
            int sv[8];
            #pragma unroll
            for (int u = 0; u < 8; u++) {
                sv[u] = s_src[w][i + u];
                wt[u] = s_ex[w][i + u] * inv;
            }
            float v0[8], v1[8];
            #pragma unroll
            for (int u = 0; u < 8; u++) {
                v0[u] = g_xp[sv[u] * 64 + lane];
                v1[u] = g_xp[sv[u] * 64 + lane + 32];
            }
            #pragma unroll
            for (int u = 0; u < 8; u++) {
                a0 += wt[u] * v0[u];
                a1 += wt[u] * v1[u];
            }
        }
        for (; i < dn; i++) {
            int s = s_src[w][i];
            float wt = s_ex[w][i] * inv;
            a0 += wt * g_xp[s * 64 + lane];
            a1 += wt * g_xp[s * 64 + lane + 32];
        }
    } else {
        for (int i = 0; i < dn; i++) {
            float4 p = g_pack[off + i];
            int s = __float_as_int(p.x);
            float se = (l == 0) ? p.y : ((l == 1) ? p.z : p.w);
            float wt = __expf(lrelu02(g_as[s] + adn + se)) * inv;
            a0 += wt * g_xp[s * 64 + lane];
            a1 += wt * g_xp[s * 64 + lane + 32];
        }
    }
    g_hjk[n * JKD + l * 64 + lane]      = lrelu001(a0 + atb[lane]);
    g_hjk[n * JKD + l * 64 + lane + 32] = lrelu001(a1 + atb[lane + 32]);
}

// ---------------- GRU recurrence: 4 (graph) tasks per CTA, 128 CTAs, 1 wave (R9) --------
#define GOFF ((size_t)NPER * G3R)
__global__ __launch_bounds__(384, 1) void gru_kernel(
    const float* __restrict__ whh_f, const float* __restrict__ bhh_f,
    const float* __restrict__ whh_b, const float* __restrict__ bhh_b)
{
    int dir = blockIdx.x >> 6;
    int quad = blockIdx.x & 63;
    const float* whh = dir ? whh_b : whh_f;
    const float* bhh = dir ? bhh_b : bhh_f;

    int tid = threadIdx.x;
    int grp = tid >> 7;
    int j   = tid & 127;

    __shared__ __align__(16) float h_s[4][128];
    __shared__ float r_s[4][128], z_s[4][128];

    unsigned long long w2[64];
    const unsigned long long* wrow = (const unsigned long long*)(whh + tid * 128);
    #pragma unroll
    for (int k = 0; k < 64; k++) w2[k] = wrow[k];
    float bh = bhh[tid];

    if (tid < 128) {
        h_s[0][tid] = 0.f; h_s[1][tid] = 0.f;
        h_s[2][tid] = 0.f; h_s[3][tid] = 0.f;
    }
    __syncthreads();

    int p = dir ? (NPER - 1) : 0;
    int dstep = dir ? -1 : 1;
    long dd = (long)dstep * G3R;

    const float* gp = g_gx[dir] + ((size_t)(quad * 4) * NPER + (size_t)p) * G3R + tid;

    float gxv0 = gp[0];
    float gxv1 = gp[GOFF];
    float gxv2 = gp[2 * GOFF];
    float gxv3 = gp[3 * GOFF];
    gp += dd;

    const ulonglong2* h2 = (const ulonglong2*)&h_s[0][0];

    for (int s = 0; s < NPER; s++) {
        float gxn0 = 0.f, gxn1 = 0.f, gxn2 = 0.f, gxn3 = 0.f;
        if (s + 1 < NPER) {
            gxn0 = gp[0];
            gxn1 = gp[GOFF];
            gxn2 = gp[2 * GOFF];
            gxn3 = gp[3 * GOFF];
            gp += dd;
        }

        unsigned long long a00 = 0, a01 = 0, a10 = 0, a11 = 0;
        unsigned long long a20 = 0, a21 = 0, a30 = 0, a31 = 0;
        #pragma unroll
        for (int k = 0; k < 32; k++) {
            unsigned long long w0 = w2[2 * k], w1 = w2[2 * k + 1];
            ulonglong2 v0 = h2[k];
            a00 = fma2(w0, v0.x, a00); a01 = fma2(w1, v0.y, a01);
            ulonglong2 v1 = h2[32 + k];
            a10 = fma2(w0, v1.x, a10); a11 = fma2(w1, v1.y, a11);
            ulonglong2 v2 = h2[64 + k];
            a20 = fma2(w0, v2.x, a20); a21 = fma2(w1, v2.y, a21);
            ulonglong2 v3 = h2[96 + k];
            a30 = fma2(w0, v3.x, a30); a31 = fma2(w1, v3.y, a31);
        }
        float ac0 = sum2(a00) + sum2(a01) + bh;
        float ac1 = sum2(a10) + sum2(a11) + bh;
        float ac2 = sum2(a20) + sum2(a21) + bh;
        float ac3 = sum2(a30) + sum2(a31) + bh;

        if (grp == 0) {
            r_s[0][j] = sigm(gxv0 + ac0);
            r_s[1][j] = sigm(gxv1 + ac1);
            r_s[2][j] = sigm(gxv2 + ac2);
            r_s[3][j] = sigm(gxv3 + ac3);
        } else if (grp == 1) {
            z_s[0][j] = sigm(gxv0 + ac0);
            z_s[1][j] = sigm(gxv1 + ac1);
            z_s[2][j] = sigm(gxv2 + ac2);
            z_s[3][j] = sigm(gxv3 + ac3);
        }
        __syncthreads();
        if (grp == 2) {
            size_t nodeB = ((size_t)(quad * 4) * NPER + (size_t)p) * 256 + dir * 128 + j;
            {
                float nv = tanh_(gxv0 + r_s[0][j] * ac0);
                float z = z_s[0][j];
                float hn = (1.f - z) * nv + z * h_s[0][j];
                h_s[0][j] = hn;
                g_y2[nodeB] = hn;
            }
            {
                float nv = tanh_(gxv1 + r_s[1][j] * ac1);
                float z = z_s[1][j];
                float hn = (1.f - z) * nv + z * h_s[1][j];
                h_s[1][j] = hn;
                g_y2[nodeB + NPER * 256] = hn;
            }
            {
                float nv = tanh_(gxv2 + r_s[2][j] * ac2);
                float z = z_s[2][j];
                float hn = (1.f - z) * nv + z * h_s[2][j];
                h_s[2][j] = hn;
                g_y2[nodeB + 2 * NPER * 256] = hn;
            }
            {
                float nv = tanh_(gxv3 + r_s[3][j] * ac3);
                float z = z_s[3][j];
                float hn = (1.f - z) * nv + z * h_s[3][j];
                h_s[3][j] = hn;
                g_y2[nodeB + 3 * NPER * 256] = hn;
            }
        }
        __syncthreads();

        gxv0 = gxn0; gxv1 = gxn1; gxv2 = gxn2; gxv3 = gxn3;
        p += dstep;
    }
}

// ---------------- launch ----------------
extern "C" void kernel_launch(void* const* d_in, const int* in_sizes, int n_in,
                              void* d_out, int out_size)
{
    const float* x         = (const float*)d_in[0];
    const float* edge_attr = (const float*)d_in[1];
    const float* node_W    = (const float*)d_in[2];
    const float* node_b    = (const float*)d_in[3];
    const float* eW        = (const float*)d_in[4];
    const float* eb        = (const float*)d_in[5];
    const float* gat_W     = (const float*)d_in[6];
    const float* gat_We    = (const float*)d_in[7];
    const float* att_s     = (const float*)d_in[8];
    const float* att_d     = (const float*)d_in[9];
    const float* att_e     = (const float*)d_in[10];
    const float* gat_b     = (const float*)d_in[11];
    const float* wih_f     = (const float*)d_in[12];
    const float* whh_f     = (const float*)d_in[13];
    const float* bih_f     = (const float*)d_in[14];
    const float* bhh_f     = (const float*)d_in[15];
    const float* wih_b     = (const float*)d_in[16];
    const float* whh_b     = (const float*)d_in[17];
    const float* bih_b     = (const float*)d_in[18];
    const float* bhh_b     = (const float*)d_in[19];
    const float* hW1       = (const float*)d_in[20];
    const float* hb1       = (const float*)d_in[21];
    const float* hW2       = (const float*)d_in[22];
    const float* hb2       = (const float*)d_in[23];
    const void*  eidx      = d_in[24];
    float* out = (float*)d_out;

    detect_kernel<<<1, 256>>>((const int*)eidx);
    zero_init_kernel<<<NN / 256, 256>>>();
    convert_edges<<<NE / 256, 256>>>(eidx);
    // 4th launch (ncu-profiled)
    tgemm3<<<dim3(1, NN / 128), 256>>>(0, 0, 64, gat_W, 64, 64, att_s, att_d,
                                       x, node_W, node_b);
    precomp_kernel<<<NL, 64>>>(gat_We, att_e, eW, eb);
    scan_kernel<<<1, 1024>>>();
    fill_csr_kernel<<<NE / 256, 256>>>(edge_attr);
    gat_agg_kernel<<<NN / 8, 256>>>(0, gat_b);

    for (int l = 1; l < NL; l++) {
        tgemm3<<<dim3(1, NN / 128), 256>>>(1, (long)(l - 1) * 64, JKD,
                                           gat_W + l * 4096, 64, 64,
                                           att_s + l * 64, att_d + l * 64,
                                           nullptr, nullptr, nullptr);
        gat_agg_kernel<<<NN / 8, 256>>>(l, gat_b + l * 64);
    }

    // gx = h_jk @ wih^T + bih, both directions (R9 fragment-major version)
    tgemmW2<<<dim3(G3R / 64, NN / 128), 256>>>(wih_f, bih_f, wih_b, bih_b);

    gru_kernel<<<128, 384>>>(whh_f, bhh_f, whh_b, bhh_b);

    // fused head: out = relu(y2 @ hW1 + hb1) @ hW2 + hb2
    tgemm<<<dim3(1, NN / 128), 256>>>(4, 0, 256, hW1, 64,
                                      0, 0, 64, 256, hb1, 2,
                                      hW2, hb2, out);
}

// round 14
// speedup vs baseline: 1.6152x; 1.6152x over previous
#include <cuda_runtime.h>
#include <math.h>

#define NN    131072      // nodes
#define NE    1048576     // edges
#define HDIM  64
#define NL    3
#define RD    128
#define JKD   192
#define BGR   256         // graphs
#define NPER  512         // nodes per graph (= seq len)
#define G3R   384         // 3*R

// ---------------- static device scratch ----------------
__device__ float g_xp[NN * HDIM];
__device__ float g_hjk[NN * JKD];
__device__ float g_as[NN];
__device__ float g_ad[NN];
__device__ int   g_deg[NN];
__device__ int   g_rowoff[NN + 1];
__device__ int   g_cursor[NN];
__device__ int   g_src[NE];
__device__ int   g_dst[NE];
__device__ float4 g_pack[NE];       // CSR-ordered {src_bits, se0, se1, se2}
__device__ float g_gx[2][(size_t)NN * G3R];
__device__ float g_y2[(size_t)NN * 256];
__device__ float g_ew[NL][2];
__device__ float g_ec[NL];
__device__ int   g_is64;

__device__ __forceinline__ float lrelu02(float x)  { return x > 0.f ? x : 0.2f  * x; }
__device__ __forceinline__ float lrelu001(float x) { return x > 0.f ? x : 0.01f * x; }
__device__ __forceinline__ float sigm(float x) { return 1.f / (1.f + __expf(-x)); }
__device__ __forceinline__ float tanh_(float x) { return 1.f - 2.f / (1.f + __expf(2.f * x)); }

__device__ __forceinline__ float* bufptr(int sel) {
    switch (sel) {
        case 1: return g_hjk;
        case 2: return g_xp;
        case 3: return g_gx[0];
        case 4: return g_y2;
    }
    return nullptr;
}

__device__ __forceinline__ unsigned f2tf(float x) {
    unsigned r;
    asm("cvt.rna.tf32.f32 %0, %1;" : "=r"(r) : "f"(x));
    return r;
}

__device__ __forceinline__ unsigned long long fma2(unsigned long long a,
                                                   unsigned long long b,
                                                   unsigned long long c) {
    unsigned long long d;
    asm("fma.rn.f32x2 %0, %1, %2, %3;" : "=l"(d) : "l"(a), "l"(b), "l"(c));
    return d;
}

__device__ __forceinline__ float sum2(unsigned long long a) {
    float x, y;
    asm("mov.b64 {%0,%1}, %2;" : "=f"(x), "=f"(y) : "l"(a));
    return x + y;
}

__device__ __forceinline__ void mma8(float* d, const unsigned* a, unsigned b0, unsigned b1) {
    asm volatile(
        "mma.sync.aligned.m16n8k8.row.col.f32.tf32.tf32.f32 "
        "{%0,%1,%2,%3}, {%4,%5,%6,%7}, {%8,%9}, {%0,%1,%2,%3};\n"
        : "+f"(d[0]), "+f"(d[1]), "+f"(d[2]), "+f"(d[3])
        : "r"(a[0]), "r"(a[1]), "r"(a[2]), "r"(a[3]), "r"(b0), "r"(b1));
}

__device__ __forceinline__ void split32(float v, unsigned& hi, unsigned& lo) {
    unsigned b = __float_as_uint(v);
    hi = b & 0xFFFFE000u;
    float l = v - __uint_as_float(hi);
    lo = f2tf(l);
}

// ---------------- small kernels ----------------
__global__ void detect_kernel(const int* raw) {
    __shared__ int s;
    int t = threadIdx.x;               // 256
    if (t == 0) s = 0;
    __syncthreads();
    if (raw[2 * t + 1] != 0) atomicOr(&s, 1);
    __syncthreads();
    if (t == 0) g_is64 = s ? 0 : 1;
}

__global__ void zero_init_kernel() {
    int i = blockIdx.x * blockDim.x + threadIdx.x;
    if (i >= NN) return;
    g_deg[i] = 0;
    g_cursor[i] = 0;
}

__global__ void convert_edges(const void* eidx) {
    int e = blockIdx.x * blockDim.x + threadIdx.x;
    if (e >= NE) return;
    int s, d;
    if (g_is64) {
        const long long* p = (const long long*)eidx;
        s = (int)p[e];
        d = (int)p[(size_t)NE + e];
    } else {
        const int* p = (const int*)eidx;
        s = p[e];
        d = p[NE + e];
    }
    g_src[e] = s;
    g_dst[e] = d;
    atomicAdd(&g_deg[d], 1);
}

// one block per layer; v = We_l @ ae_l, then 3 dot products
__global__ void precomp_kernel(const float* __restrict__ We, const float* __restrict__ ae,
                               const float* __restrict__ eW, const float* __restrict__ eb) {
    __shared__ float v[64];
    int l = blockIdx.x;
    int t = threadIdx.x;   // 64
    float s = 0.f;
    #pragma unroll
    for (int j = 0; j < 64; j++) s += We[l * 4096 + t * 64 + j] * ae[l * 64 + j];
    v[t] = s;
    __syncthreads();
    if (t < 32) {
        float e0 = 0.f, e1 = 0.f, c = 0.f;
        #pragma unroll
        for (int k = t; k < 64; k += 32) {
            e0 += eW[k]      * v[k];
            e1 += eW[64 + k] * v[k];
            c  += eb[k]      * v[k];
        }
        #pragma unroll
        for (int o = 16; o; o >>= 1) {
            e0 += __shfl_xor_sync(~0u, e0, o);
            e1 += __shfl_xor_sync(~0u, e1, o);
            c  += __shfl_xor_sync(~0u, c, o);
        }
        if (t == 0) { g_ew[l][0] = e0; g_ew[l][1] = e1; g_ec[l] = c; }
    }
}

__global__ void scan_kernel() {
    __shared__ int sh[1024];
    int tid = threadIdx.x;
    int base = tid * (NN / 1024);
    int s = 0;
    for (int i = 0; i < NN / 1024; i++) s += g_deg[base + i];
    sh[tid] = s;
    __syncthreads();
    for (int off = 1; off < 1024; off <<= 1) {
        int v = (tid >= off) ? sh[tid - off] : 0;
        __syncthreads();
        sh[tid] += v;
        __syncthreads();
    }
    int run = sh[tid] - s;
    for (int i = 0; i < NN / 1024; i++) {
        g_rowoff[base + i] = run;
        run += g_deg[base + i];
    }
    if (tid == 1023) g_rowoff[NN] = sh[1023];
}

// CSR fill: ONE 16B packed store per edge {src, se0, se1, se2}
__global__ void fill_csr_kernel(const float* __restrict__ edge_attr) {
    int e = blockIdx.x * blockDim.x + threadIdx.x;
    if (e >= NE) return;
    int d = g_dst[e];
    int pos = g_rowoff[d] + atomicAdd(&g_cursor[d], 1);
    float ea0 = edge_attr[2 * e], ea1 = edge_attr[2 * e + 1];
    float4 p;
    p.x = __int_as_float(g_src[e]);
    p.y = ea0 * g_ew[0][0] + ea1 * g_ew[0][1] + g_ec[0];
    p.z = ea0 * g_ew[1][0] + ea1 * g_ew[1][1] + g_ec[1];
    p.w = ea0 * g_ew[2][0] + ea1 * g_ew[2][1] + g_ec[2];
    g_pack[pos] = p;
}

// ---------------- tf32 tensor-core GEMM: 128x64 tile, double-buffered (head path) ---------
#define PADA 136
#define PADB 72
__global__ __launch_bounds__(256) void tgemm(
    int Asel, long aoff, int lda,
    const float* __restrict__ B, int ldb,
    int Csel, long coff, int ldc, int K,
    const float* __restrict__ bias, int act,
    const float* __restrict__ W2, const float* __restrict__ b2,
    float* __restrict__ outp)
{
    const float* A = bufptr(Asel) + aoff;
    float*       C = (act == 2) ? nullptr : (bufptr(Csel) + coff);

    __shared__ unsigned As[2][16][PADA];
    __shared__ unsigned Bs[2][16][PADB];
    __shared__ float sm_o[128][2];

    int tid = threadIdx.x;
    int warp = tid >> 5, lane = tid & 31;
    int wm = (warp & 3) * 32;
    int wn = (warp >> 2) * 32;
    int g = lane >> 2, tg = lane & 3;

    long mBase = (long)blockIdx.y * 128;
    int  nBase = blockIdx.x * 64;

    float acc[2][4][4] = {};

    int arow = tid >> 1, acol = (tid & 1) * 8;
    const float* Aptr = A + (mBase + arow) * lda + acol;
    int bkN = tid >> 4, bnN = (tid & 15) * 4;

    int T = K / 16;

    float4 sa0, sa1, sb;
    sa0 = *(const float4*)(Aptr);
    sa1 = *(const float4*)(Aptr + 4);
    sb  = *(const float4*)(B + (long)bkN * ldb + nBase + bnN);

    As[0][acol + 0][arow] = f2tf(sa0.x);
    As[0][acol + 1][arow] = f2tf(sa0.y);
    As[0][acol + 2][arow] = f2tf(sa0.z);
    As[0][acol + 3][arow] = f2tf(sa0.w);
    As[0][acol + 4][arow] = f2tf(sa1.x);
    As[0][acol + 5][arow] = f2tf(sa1.y);
    As[0][acol + 6][arow] = f2tf(sa1.z);
    As[0][acol + 7][arow] = f2tf(sa1.w);
    Bs[0][bkN][bnN + 0] = f2tf(sb.x);
    Bs[0][bkN][bnN + 1] = f2tf(sb.y);
    Bs[0][bkN][bnN + 2] = f2tf(sb.z);
    Bs[0][bkN][bnN + 3] = f2tf(sb.w);
    __syncthreads();

    for (int t = 0; t < T; t++) {
        int buf = t & 1;
        if (t + 1 < T) {
            int kt = (t + 1) * 16;
            sa0 = *(const float4*)(Aptr + kt);
            sa1 = *(const float4*)(Aptr + kt + 4);
            sb  = *(const float4*)(B + (long)(kt + bkN) * ldb + nBase + bnN);
        }

        #pragma unroll
        for (int kk = 0; kk < 16; kk += 8) {
            unsigned a[2][4], b[4][2];
            #pragma unroll
            for (int mi = 0; mi < 2; mi++) {
                int m0 = wm + mi * 16;
                a[mi][0] = As[buf][kk + tg]    [m0 + g];
                a[mi][1] = As[buf][kk + tg]    [m0 + g + 8];
                a[mi][2] = As[buf][kk + tg + 4][m0 + g];
                a[mi][3] = As[buf][kk + tg + 4][m0 + g + 8];
            }
            #pragma unroll
            for (int ni = 0; ni < 4; ni++) {
                b[ni][0] = Bs[buf][kk + tg]    [wn + ni * 8 + g];
                b[ni][1] = Bs[buf][kk + tg + 4][wn + ni * 8 + g];
            }
            #pragma unroll
            for (int mi = 0; mi < 2; mi++)
                #pragma unroll
                for (int ni = 0; ni < 4; ni++)
                    mma8(acc[mi][ni], a[mi], b[ni][0], b[ni][1]);
        }

        if (t + 1 < T) {
            int nb = buf ^ 1;
            As[nb][acol + 0][arow] = f2tf(sa0.x);
            As[nb][acol + 1][arow] = f2tf(sa0.y);
            As[nb][acol + 2][arow] = f2tf(sa0.z);
            As[nb][acol + 3][arow] = f2tf(sa0.w);
            As[nb][acol + 4][arow] = f2tf(sa1.x);
            As[nb][acol + 5][arow] = f2tf(sa1.y);
            As[nb][acol + 6][arow] = f2tf(sa1.z);
            As[nb][acol + 7][arow] = f2tf(sa1.w);
            Bs[nb][bkN][bnN + 0] = f2tf(sb.x);
            Bs[nb][bkN][bnN + 1] = f2tf(sb.y);
            Bs[nb][bkN][bnN + 2] = f2tf(sb.z);
            Bs[nb][bkN][bnN + 3] = f2tf(sb.w);
        }
        __syncthreads();
    }

    if (act == 2) {
        if (tid < 128) { sm_o[tid][0] = 0.f; sm_o[tid][1] = 0.f; }
        __syncthreads();
        float po[2][2][2] = {};
        #pragma unroll
        for (int mi = 0; mi < 2; mi++)
            #pragma unroll
            for (int ni = 0; ni < 4; ni++) {
                int col = nBase + wn + ni * 8 + tg * 2;
                float b0 = bias[col], b1 = bias[col + 1];
                float w00 = W2[col * 2],       w01 = W2[col * 2 + 1];
                float w10 = W2[(col + 1) * 2], w11 = W2[(col + 1) * 2 + 1];
                #pragma unroll
                for (int r = 0; r < 2; r++) {
                    float v0 = fmaxf(acc[mi][ni][2 * r]     + b0, 0.f);
                    float v1 = fmaxf(acc[mi][ni][2 * r + 1] + b1, 0.f);
                    po[mi][r][0] += v0 * w00 + v1 * w10;
                    po[mi][r][1] += v0 * w01 + v1 * w11;
                }
            }
        #pragma unroll
        for (int mi = 0; mi < 2; mi++)
            #pragma unroll
            for (int r = 0; r < 2; r++)
                #pragma unroll
                for (int o = 0; o < 2; o++) {
                    po[mi][r][o] += __shfl_xor_sync(~0u, po[mi][r][o], 1);
                    po[mi][r][o] += __shfl_xor_sync(~0u, po[mi][r][o], 2);
                }
        if (tg == 0) {
            #pragma unroll
            for (int mi = 0; mi < 2; mi++)
                #pragma unroll
                for (int r = 0; r < 2; r++) {
                    int rl = wm + mi * 16 + g + r * 8;
                    atomicAdd(&sm_o[rl][0], po[mi][r][0]);
                    atomicAdd(&sm_o[rl][1], po[mi][r][1]);
                }
        }
        __syncthreads();
        if (tid < 128) {
            long row = mBase + tid;
            *(float2*)(outp + row * 2) =
                make_float2(sm_o[tid][0] + b2[0], sm_o[tid][1] + b2[1]);
        }
        return;
    }

    #pragma unroll
    for (int mi = 0; mi < 2; mi++)
        #pragma unroll
        for (int ni = 0; ni < 4; ni++) {
            int col = nBase + wn + ni * 8 + tg * 2;
            float b0 = bias ? bias[col]     : 0.f;
            float b1 = bias ? bias[col + 1] : 0.f;
            #pragma unroll
            for (int r = 0; r < 2; r++) {
                long row = mBase + wm + mi * 16 + g + r * 8;
                float v0 = acc[mi][ni][2 * r]     + b0;
                float v1 = acc[mi][ni][2 * r + 1] + b1;
                if (act == 1) { v0 = fmaxf(v0, 0.f); v1 = fmaxf(v1, 0.f); }
                *(float2*)(C + row * ldc + col) = make_float2(v0, v1);
            }
        }
}

// ---------------- wih GEMM, BOTH directions, fragment-major smem layout (R9 version) ----
__global__ __launch_bounds__(256) void tgemmW2(
    const float* __restrict__ Bf, const float* __restrict__ biasf,
    const float* __restrict__ Bb, const float* __restrict__ biasb)
{
    __shared__ __align__(16) unsigned Af[2][8][2][136];
    __shared__ __align__(8)  unsigned BsF[2][8][2][68];
    __shared__ __align__(8)  unsigned BsB[2][8][2][68];

    int tid = threadIdx.x;
    int warp = tid >> 5, lane = tid & 31;
    int mtb = (warp & 3) * 2;
    int ntb = (warp >> 2) * 4;

    long mBase = (long)blockIdx.y * 128;
    int  nBase = blockIdx.x * 64;

    float accF[2][4][4] = {};
    float accB[2][4][4] = {};

    int arow = tid >> 1, ab = tid & 1;
    int amt = arow >> 4, ag = arow & 7, arh = (arow >> 3) & 1;
    const float* Aptr = g_hjk + (mBase + arow) * JKD + ab * 8;

    int bn = tid >> 2;
    int bb_ = (tid & 3) >> 1, bh = tid & 1;
    int bnt = bn >> 3, bg = bn & 7;
    const float* BfPtr = Bf + (long)(nBase + bn) * JKD + bb_ * 8 + bh * 4;
    const float* BbPtr = Bb + (long)(nBase + bn) * JKD + bb_ * 8 + bh * 4;

    const int T = JKD / 16;

    float4 sa0 = *(const float4*)(Aptr);
    float4 sa1 = *(const float4*)(Aptr + 4);
    float4 sbf = *(const float4*)(BfPtr);
    float4 sbb = *(const float4*)(BbPtr);

    {
        float va[8] = {sa0.x, sa0.y, sa0.z, sa0.w, sa1.x, sa1.y, sa1.z, sa1.w};
        #pragma unroll
        for (int j = 0; j < 8; j++) {
            int tg = j & 3, h = j >> 2;
            Af[0][amt][ab][(ag * 4 + tg) * 4 + arh + 2 * h] = f2tf(va[j]);
        }
        float vf[4] = {sbf.x, sbf.y, sbf.z, sbf.w};
        float vb[4] = {sbb.x, sbb.y, sbb.z, sbb.w};
        #pragma unroll
        for (int tg = 0; tg < 4; tg++) {
            BsF[0][bnt][bb_][(bg * 4 + tg) * 2 + bh] = f2tf(vf[tg]);
            BsB[0][bnt][bb_][(bg * 4 + tg) * 2 + bh] = f2tf(vb[tg]);
        }
    }
    __syncthreads();

    for (int t = 0; t < T; t++) {
        int buf = t & 1;
        if (t + 1 < T) {
            int kt = (t + 1) * 16;
            sa0 = *(const float4*)(Aptr + kt);
            sa1 = *(const float4*)(Aptr + kt + 4);
            sbf = *(const float4*)(BfPtr + kt);
            sbb = *(const float4*)(BbPtr + kt);
        }

        #pragma unroll
        for (int b = 0; b < 2; b++) {
            unsigned a[2][4];
            uint2 fb[4], bbr[4];
            #pragma unroll
            for (int mi = 0; mi < 2; mi++)
                *(uint4*)a[mi] = *(const uint4*)&Af[buf][mtb + mi][b][lane * 4];
            #pragma unroll
            for (int ni = 0; ni < 4; ni++) {
                fb[ni]  = *(const uint2*)&BsF[buf][ntb + ni][b][lane * 2];
                bbr[ni] = *(const uint2*)&BsB[buf][ntb + ni][b][lane * 2];
            }
            #pragma unroll
            for (int mi = 0; mi < 2; mi++)
                #pragma unroll
                for (int ni = 0; ni < 4; ni++) {
                    mma8(accF[mi][ni], a[mi], fb[ni].x, fb[ni].y);
                    mma8(accB[mi][ni], a[mi], bbr[ni].x, bbr[ni].y);
                }
        }

        if (t + 1 < T) {
            int nb = buf ^ 1;
            float va[8] = {sa0.x, sa0.y, sa0.z, sa0.w, sa1.x, sa1.y, sa1.z, sa1.w};
            #pragma unroll
            for (int j = 0; j < 8; j++) {
                int tg = j & 3, h = j >> 2;
                Af[nb][amt][ab][(ag * 4 + tg) * 4 + arh + 2 * h] = f2tf(va[j]);
            }
            float vf[4] = {sbf.x, sbf.y, sbf.z, sbf.w};
            float vb[4] = {sbb.x, sbb.y, sbb.z, sbb.w};
            #pragma unroll
            for (int tg = 0; tg < 4; tg++) {
                BsF[nb][bnt][bb_][(bg * 4 + tg) * 2 + bh] = f2tf(vf[tg]);
                BsB[nb][bnt][bb_][(bg * 4 + tg) * 2 + bh] = f2tf(vb[tg]);
            }
        }
        __syncthreads();
    }

    int g = lane >> 2, tg = lane & 3;
    float* Cf = g_gx[0];
    float* Cb = g_gx[1];
    #pragma unroll
    for (int mi = 0; mi < 2; mi++)
        #pragma unroll
        for (int ni = 0; ni < 4; ni++) {
            int col = nBase + (ntb + ni) * 8 + tg * 2;
            float bf0 = biasf[col], bf1 = biasf[col + 1];
            float bb0 = biasb[col], bb1 = biasb[col + 1];
            #pragma unroll
            for (int r = 0; r < 2; r++) {
                long row = mBase + (mtb + mi) * 16 + g + r * 8;
                *(float2*)(Cf + row * G3R + col) =
                    make_float2(accF[mi][ni][2 * r] + bf0, accF[mi][ni][2 * r + 1] + bf1);
                *(float2*)(Cb + row * G3R + col) =
                    make_float2(accB[mi][ni][2 * r] + bb0, accB[mi][ni][2 * r + 1] + bb1);
            }
        }
}

// ---------------- 3xTF32 GEMM (fp32-accurate) for GAT xp, fused a_s/a_d epilogue -------
__global__ __launch_bounds__(256) void tgemm3(
    int Asel, long aoff, int lda,
    const float* __restrict__ B, int ldb, int K,
    const float* __restrict__ atts, const float* __restrict__ attd,
    const float* __restrict__ x, const float* __restrict__ nW,
    const float* __restrict__ nb)
{
    float* C = g_xp;

    __shared__ unsigned Ah[16][PADA], Al[16][PADA];
    __shared__ unsigned Bh[16][PADB], Bl[16][PADB];
    __shared__ float sm_ad[128][2];

    int tid = threadIdx.x;
    int warp = tid >> 5, lane = tid & 31;
    int wm = (warp & 3) * 32;
    int wn = (warp >> 2) * 32;
    int g = lane >> 2, tg = lane & 3;

    long mBase = (long)blockIdx.y * 128;
    int  nBase = blockIdx.x * 64;

    float acc[2][4][4] = {};

    int arow = tid >> 1, acol = (tid & 1) * 8;
    bool emb = (Asel == 0);
    const float* Aptr = emb ? nullptr : (bufptr(Asel) + aoff + (mBase + arow) * lda + acol);
    float2 xr = emb ? *(const float2*)(x + 2 * (mBase + arow)) : make_float2(0.f, 0.f);
    int bkN = tid >> 4, bnN = (tid & 15) * 4;

    if (tid < 128) { sm_ad[tid][0] = 0.f; sm_ad[tid][1] = 0.f; }

    for (int kt = 0; kt < K; kt += 16) {
        float va[8];
        if (emb) {
            #pragma unroll
            for (int j = 0; j < 8; j++) {
                int c = kt + acol + j;
                va[j] = xr.x * nW[c] + xr.y * nW[64 + c] + nb[c];
            }
        } else {
            float4 a0 = *(const float4*)(Aptr + kt);
            float4 a1 = *(const float4*)(Aptr + kt + 4);
            va[0] = a0.x; va[1] = a0.y; va[2] = a0.z; va[3] = a0.w;
            va[4] = a1.x; va[5] = a1.y; va[6] = a1.z; va[7] = a1.w;
        }
        float4 b4 = *(const float4*)(B + (long)(kt + bkN) * ldb + nBase + bnN);
        __syncthreads();

        unsigned h, l;
        #pragma unroll
        for (int j = 0; j < 8; j++) {
            split32(va[j], h, l);
            Ah[acol + j][arow] = h; Al[acol + j][arow] = l;
        }
        split32(b4.x, h, l); Bh[bkN][bnN + 0] = h; Bl[bkN][bnN + 0] = l;
        split32(b4.y, h, l); Bh[bkN][bnN + 1] = h; Bl[bkN][bnN + 1] = l;
        split32(b4.z, h, l); Bh[bkN][bnN + 2] = h; Bl[bkN][bnN + 2] = l;
        split32(b4.w, h, l); Bh[bkN][bnN + 3] = h; Bl[bkN][bnN + 3] = l;
        __syncthreads();

        #pragma unroll
        for (int kk = 0; kk < 16; kk += 8) {
            unsigned ah[2][4], al[2][4], bh[4][2], bl[4][2];
            #pragma unroll
            for (int mi = 0; mi < 2; mi++) {
                int m0 = wm + mi * 16;
                ah[mi][0] = Ah[kk + tg]    [m0 + g];
                ah[mi][1] = Ah[kk + tg]    [m0 + g + 8];
                ah[mi][2] = Ah[kk + tg + 4][m0 + g];
                ah[mi][3] = Ah[kk + tg + 4][m0 + g + 8];
                al[mi][0] = Al[kk + tg]    [m0 + g];
                al[mi][1] = Al[kk + tg]    [m0 + g + 8];
                al[mi][2] = Al[kk + tg + 4][m0 + g];
                al[mi][3] = Al[kk + tg + 4][m0 + g + 8];
            }
            #pragma unroll
            for (int ni = 0; ni < 4; ni++) {
                bh[ni][0] = Bh[kk + tg]    [wn + ni * 8 + g];
                bh[ni][1] = Bh[kk + tg + 4][wn + ni * 8 + g];
                bl[ni][0] = Bl[kk + tg]    [wn + ni * 8 + g];
                bl[ni][1] = Bl[kk + tg + 4][wn + ni * 8 + g];
            }
            #pragma unroll
            for (int mi = 0; mi < 2; mi++)
                #pragma unroll
                for (int ni = 0; ni < 4; ni++) {
                    mma8(acc[mi][ni], ah[mi], bh[ni][0], bh[ni][1]);
                    mma8(acc[mi][ni], ah[mi], bl[ni][0], bl[ni][1]);
                    mma8(acc[mi][ni], al[mi], bh[ni][0], bh[ni][1]);
                }
        }
    }

    float ps[2][2] = {}, pd[2][2] = {};
    #pragma unroll
    for (int mi = 0; mi < 2; mi++)
        #pragma unroll
        for (int ni = 0; ni < 4; ni++) {
            int col = nBase + wn + ni * 8 + tg * 2;
            float as0 = atts[col], as1 = atts[col + 1];
            float ad0 = attd[col], ad1 = attd[col + 1];
            #pragma unroll
            for (int r = 0; r < 2; r++) {
                long row = mBase + wm + mi * 16 + g + r * 8;
                float v0 = acc[mi][ni][2 * r], v1 = acc[mi][ni][2 * r + 1];
                *(float2*)(C + row * 64 + col) = make_float2(v0, v1);
                ps[mi][r] += v0 * as0 + v1 * as1;
                pd[mi][r] += v0 * ad0 + v1 * ad1;
            }
        }
    #pragma unroll
    for (int mi = 0; mi < 2; mi++)
        #pragma unroll
        for (int r = 0; r < 2; r++) {
            ps[mi][r] += __shfl_xor_sync(~0u, ps[mi][r], 1);
            ps[mi][r] += __shfl_xor_sync(~0u, ps[mi][r], 2);
            pd[mi][r] += __shfl_xor_sync(~0u, pd[mi][r], 1);
            pd[mi][r] += __shfl_xor_sync(~0u, pd[mi][r], 2);
        }
    if (tg == 0) {
        #pragma unroll
        for (int mi = 0; mi < 2; mi++)
            #pragma unroll
            for (int r = 0; r < 2; r++) {
                int rl = wm + mi * 16 + g + r * 8;
                atomicAdd(&sm_ad[rl][0], ps[mi][r]);
                atomicAdd(&sm_ad[rl][1], pd[mi][r]);
            }
    }
    __syncthreads();
    if (tid < 128) {
        g_as[mBase + tid] = sm_ad[tid][0];
        g_ad[mBase + tid] = sm_ad[tid][1];
    }
}

// GAT softmax + aggregation: 2-pass (no max subtraction; alphas are O(0.1), exp safe)
#define MAXDN 64
__global__ void gat_agg_kernel(int l, const float* __restrict__ atb) {
    int w = threadIdx.x >> 5, lane = threadIdx.x & 31;
    int n = blockIdx.x * 8 + w;
    if (n >= NN) return;

    __shared__ float s_ex[8][MAXDN];
    __shared__ int   s_src[8][MAXDN];

    int off = g_rowoff[n];
    int dn = g_rowoff[n + 1] - off;
    float adn = g_ad[n];
    bool cached = (dn <= MAXDN);

    // pass A: exp(alpha) directly, accumulate den and sum_se
    float den = 0.f, sum_se = 0.f;
    for (int i = lane; i < dn; i += 32) {
        float4 p = g_pack[off + i];
        int s = __float_as_int(p.x);
        float se = (l == 0) ? p.y : ((l == 1) ? p.z : p.w);
        float ex = __expf(lrelu02(g_as[s] + adn + se));
        sum_se += se;
        den += ex;
        if (cached) { s_ex[w][i] = ex; s_src[w][i] = s; }
    }
    #pragma unroll
    for (int o = 16; o; o >>= 1) {
        den += __shfl_xor_sync(~0u, den, o);
        sum_se += __shfl_xor_sync(~0u, sum_se, o);
    }
    float loopv = sum_se / (float)max(dn, 1);
    float eself = __expf(lrelu02(g_as[n] + adn + loopv));
    den += eself;
    float inv = 1.f / den;
    __syncwarp();

    // pass B: weighted aggregation, 4-wide unroll (proven R9 loop shape)
    float a0 = eself * inv * g_xp[n * 64 + lane];
    float a1 = eself * inv * g_xp[n * 64 + lane + 32];
    if (cached) {
        int i = 0;
        for (; i + 4 <= dn; i += 4) {
            int s0 = s_src[w][i],     s1 = s_src[w][i + 1];
            int s2 = s_src[w][i + 2], s3 = s_src[w][i + 3];
            float w0 = s_ex[w][i] * inv,     w1 = s_ex[w][i + 1] * inv;
            float w2 = s_ex[w][i + 2] * inv, w3 = s_ex[w][i + 3] * inv;
            float v00 = g_xp[s0 * 64 + lane], v01 = g_xp[s0 * 64 + lane + 32];
            float v10 = g_xp[s1 * 64 + lane], v11 = g_xp[s1 * 64 + lane + 32];
            float v20 = g_xp[s2 * 64 + lane], v21 = g_xp[s2 * 64 + lane + 32];
            float v30 = g_xp[s3 * 64 + lane], v31 = g_xp[s3 * 64 + lane + 32];
            a0 += w0 * v00 + w1 * v10 + w2 * v20 + w3 * v30;
            a1 += w0 * v01 + w1 * v11 + w2 * v21 + w3 * v31;
        }
        for (; i < dn; i++) {
            int s = s_src[w][i];
            float wt = s_ex[w][i] * inv;
            a0 += wt * g_xp[s * 64 + lane];
            a1 += wt * g_xp[s * 64 + lane + 32];
        }
    } else {
        for (int i = 0; i < dn; i++) {
            float4 p = g_pack[off + i];
            int s = __float_as_int(p.x);
            float se = (l == 0) ? p.y : ((l == 1) ? p.z : p.w);
            float wt = __expf(lrelu02(g_as[s] + adn + se)) * inv;
            a0 += wt * g_xp[s * 64 + lane];
            a1 += wt * g_xp[s * 64 + lane + 32];
        }
    }
    g_hjk[n * JKD + l * 64 + lane]      = lrelu001(a0 + atb[lane]);
    g_hjk[n * JKD + l * 64 + lane + 32] = lrelu001(a1 + atb[lane + 32]);
}

// ---------------- GRU recurrence: 4 (graph) tasks per CTA, 128 CTAs, 1 wave (R9) --------
#define GOFF ((size_t)NPER * G3R)
__global__ __launch_bounds__(384, 1) void gru_kernel(
    const float* __restrict__ whh_f, const float* __restrict__ bhh_f,
    const float* __restrict__ whh_b, const float* __restrict__ bhh_b)
{
    int dir = blockIdx.x >> 6;
    int quad = blockIdx.x & 63;
    const float* whh = dir ? whh_b : whh_f;
    const float* bhh = dir ? bhh_b : bhh_f;

    int tid = threadIdx.x;
    int grp = tid >> 7;
    int j   = tid & 127;

    __shared__ __align__(16) float h_s[4][128];
    __shared__ float r_s[4][128], z_s[4][128];

    unsigned long long w2[64];
    const unsigned long long* wrow = (const unsigned long long*)(whh + tid * 128);
    #pragma unroll
    for (int k = 0; k < 64; k++) w2[k] = wrow[k];
    float bh = bhh[tid];

    if (tid < 128) {
        h_s[0][tid] = 0.f; h_s[1][tid] = 0.f;
        h_s[2][tid] = 0.f; h_s[3][tid] = 0.f;
    }
    __syncthreads();

    int p = dir ? (NPER - 1) : 0;
    int dstep = dir ? -1 : 1;
    long dd = (long)dstep * G3R;

    const float* gp = g_gx[dir] + ((size_t)(quad * 4) * NPER + (size_t)p) * G3R + tid;

    float gxv0 = gp[0];
    float gxv1 = gp[GOFF];
    float gxv2 = gp[2 * GOFF];
    float gxv3 = gp[3 * GOFF];
    gp += dd;

    const ulonglong2* h2 = (const ulonglong2*)&h_s[0][0];

    for (int s = 0; s < NPER; s++) {
        float gxn0 = 0.f, gxn1 = 0.f, gxn2 = 0.f, gxn3 = 0.f;
        if (s + 1 < NPER) {
            gxn0 = gp[0];
            gxn1 = gp[GOFF];
            gxn2 = gp[2 * GOFF];
            gxn3 = gp[3 * GOFF];
            gp += dd;
        }

        unsigned long long a00 = 0, a01 = 0, a10 = 0, a11 = 0;
        unsigned long long a20 = 0, a21 = 0, a30 = 0, a31 = 0;
        #pragma unroll
        for (int k = 0; k < 32; k++) {
            unsigned long long w0 = w2[2 * k], w1 = w2[2 * k + 1];
            ulonglong2 v0 = h2[k];
            a00 = fma2(w0, v0.x, a00); a01 = fma2(w1, v0.y, a01);
            ulonglong2 v1 = h2[32 + k];
            a10 = fma2(w0, v1.x, a10); a11 = fma2(w1, v1.y, a11);
            ulonglong2 v2 = h2[64 + k];
            a20 = fma2(w0, v2.x, a20); a21 = fma2(w1, v2.y, a21);
            ulonglong2 v3 = h2[96 + k];
            a30 = fma2(w0, v3.x, a30); a31 = fma2(w1, v3.y, a31);
        }
        float ac0 = sum2(a00) + sum2(a01) + bh;
        float ac1 = sum2(a10) + sum2(a11) + bh;
        float ac2 = sum2(a20) + sum2(a21) + bh;
        float ac3 = sum2(a30) + sum2(a31) + bh;

        if (grp == 0) {
            r_s[0][j] = sigm(gxv0 + ac0);
            r_s[1][j] = sigm(gxv1 + ac1);
            r_s[2][j] = sigm(gxv2 + ac2);
            r_s[3][j] = sigm(gxv3 + ac3);
        } else if (grp == 1) {
            z_s[0][j] = sigm(gxv0 + ac0);
            z_s[1][j] = sigm(gxv1 + ac1);
            z_s[2][j] = sigm(gxv2 + ac2);
            z_s[3][j] = sigm(gxv3 + ac3);
        }
        __syncthreads();
        if (grp == 2) {
            size_t nodeB = ((size_t)(quad * 4) * NPER + (size_t)p) * 256 + dir * 128 + j;
            {
                float nv = tanh_(gxv0 + r_s[0][j] * ac0);
                float z = z_s[0][j];
                float hn = (1.f - z) * nv + z * h_s[0][j];
                h_s[0][j] = hn;
                g_y2[nodeB] = hn;
            }
            {
                float nv = tanh_(gxv1 + r_s[1][j] * ac1);
                float z = z_s[1][j];
                float hn = (1.f - z) * nv + z * h_s[1][j];
                h_s[1][j] = hn;
                g_y2[nodeB + NPER * 256] = hn;
            }
            {
                float nv = tanh_(gxv2 + r_s[2][j] * ac2);
                float z = z_s[2][j];
                float hn = (1.f - z) * nv + z * h_s[2][j];
                h_s[2][j] = hn;
                g_y2[nodeB + 2 * NPER * 256] = hn;
            }
            {
                float nv = tanh_(gxv3 + r_s[3][j] * ac3);
                float z = z_s[3][j];
                float hn = (1.f - z) * nv + z * h_s[3][j];
                h_s[3][j] = hn;
                g_y2[nodeB + 3 * NPER * 256] = hn;
            }
        }
        __syncthreads();

        gxv0 = gxn0; gxv1 = gxn1; gxv2 = gxn2; gxv3 = gxn3;
        p += dstep;
    }
}

// ---------------- launch ----------------
extern "C" void kernel_launch(void* const* d_in, const int* in_sizes, int n_in,
                              void* d_out, int out_size)
{
    const float* x         = (const float*)d_in[0];
    const float* edge_attr = (const float*)d_in[1];
    const float* node_W    = (const float*)d_in[2];
    const float* node_b    = (const float*)d_in[3];
    const float* eW        = (const float*)d_in[4];
    const float* eb        = (const float*)d_in[5];
    const float* gat_W     = (const float*)d_in[6];
    const float* gat_We    = (const float*)d_in[7];
    const float* att_s     = (const float*)d_in[8];
    const float* att_d     = (const float*)d_in[9];
    const float* att_e     = (const float*)d_in[10];
    const float* gat_b     = (const float*)d_in[11];
    const float* wih_f     = (const float*)d_in[12];
    const float* whh_f     = (const float*)d_in[13];
    const float* bih_f     = (const float*)d_in[14];
    const float* bhh_f     = (const float*)d_in[15];
    const float* wih_b     = (const float*)d_in[16];
    const float* whh_b     = (const float*)d_in[17];
    const float* bih_b     = (const float*)d_in[18];
    const float* bhh_b     = (const float*)d_in[19];
    const float* hW1       = (const float*)d_in[20];
    const float* hb1       = (const float*)d_in[21];
    const float* hW2       = (const float*)d_in[22];
    const float* hb2       = (const float*)d_in[23];
    const void*  eidx      = d_in[24];
    float* out = (float*)d_out;

    detect_kernel<<<1, 256>>>((const int*)eidx);
    zero_init_kernel<<<NN / 256, 256>>>();
    convert_edges<<<NE / 256, 256>>>(eidx);
    // 4th launch (ncu-profiled): clock canary (33 us at full clock, ~50 us throttled)
    tgemm3<<<dim3(1, NN / 128), 256>>>(0, 0, 64, gat_W, 64, 64, att_s, att_d,
                                       x, node_W, node_b);
    precomp_kernel<<<NL, 64>>>(gat_We, att_e, eW, eb);
    scan_kernel<<<1, 1024>>>();
    fill_csr_kernel<<<NE / 256, 256>>>(edge_attr);
    gat_agg_kernel<<<NN / 8, 256>>>(0, gat_b);

    for (int l = 1; l < NL; l++) {
        tgemm3<<<dim3(1, NN / 128), 256>>>(1, (long)(l - 1) * 64, JKD,
                                           gat_W + l * 4096, 64, 64,
                                           att_s + l * 64, att_d + l * 64,
                                           nullptr, nullptr, nullptr);
        gat_agg_kernel<<<NN / 8, 256>>>(l, gat_b + l * 64);
    }

    // gx = h_jk @ wih^T + bih, both directions (R9 fragment-major version)
    tgemmW2<<<dim3(G3R / 64, NN / 128), 256>>>(wih_f, bih_f, wih_b, bih_b);

    gru_kernel<<<128, 384>>>(whh_f, bhh_f, whh_b, bhh_b);

    // fused head: out = relu(y2 @ hW1 + hb1) @ hW2 + hb2
    tgemm<<<dim3(1, NN / 128), 256>>>(4, 0, 256, hW1, 64,
                                      0, 0, 64, 256, hb1, 2,
                                      hW2, hb2, out);
}